// round 1
// baseline (speedup 1.0000x reference)
#include <cuda_runtime.h>
#include <math.h>

// Problem constants
#define TT   1024   // tokens
#define HH   1024   // hidden
#define EE   8      // experts
#define II   1024   // intermediate (per half)
#define KK   2      // top_k
#define NP   (TT*KK) // 2048 (token, slot) pairs

// GEMM tiling
#define TM   64
#define TN   64
#define TKB  32
#define AS_LD 68     // padded lead dim for k-major A tile (conflict mitigation)
#define MAX_TILES 40 // sum ceil(cnt_e/64) <= 2048/64 + 7 = 39

// ---------------- scratch (device globals; no allocation allowed) ----------
__device__ int   g_counts[EE];
__device__ int   g_offsets[EE];
__device__ int   g_cursor[EE];
__device__ int   g_list[NP];     // sorted-by-expert list; entry = t*2 + k
__device__ int   g_pos[NP];      // inverse map: pos_of[t*2+k] = p
__device__ float g_w[NP];        // routing weight for (t,k)
__device__ int   g_tile_e[MAX_TILES];
__device__ int   g_tile_row[MAX_TILES];
__device__ int   g_tile_rows[MAX_TILES];
__device__ int   g_ntiles;
__device__ __align__(16) float g_act[(size_t)NP * II];   // 8 MB: silu(gate)*up, sorted-position rows
__device__ __align__(16) float g_down[(size_t)NP * HH];  // 8 MB: pre-weighted down output

// ---------------- routing: top-2 + renorm + expert grouping ----------------
__global__ void route_kernel(const float* __restrict__ logits)
{
    int t = threadIdx.x;      // one token per thread, 1024 threads, 1 block
    if (t < EE) { g_counts[t] = 0; }
    __syncthreads();

    float l[EE];
#pragma unroll
    for (int e = 0; e < EE; e++) l[e] = logits[t * EE + e];

    // argmax (ties -> lowest index, matching jax.lax.top_k)
    int i0 = 0;
#pragma unroll
    for (int e = 1; e < EE; e++) if (l[e] > l[i0]) i0 = e;
    int i1 = (i0 == 0) ? 1 : 0;
#pragma unroll
    for (int e = 0; e < EE; e++) if (e != i0 && l[e] > l[i1]) i1 = e;

    // renormalized top-2 softmax: softmax denom cancels
    float e1 = __expf(l[i1] - l[i0]);
    float inv = 1.0f / (1.0f + e1);
    g_w[t * 2 + 0] = inv;
    g_w[t * 2 + 1] = e1 * inv;

    atomicAdd(&g_counts[i0], 1);
    atomicAdd(&g_counts[i1], 1);
    __syncthreads();

    if (t == 0) {
        int off = 0;
        for (int e = 0; e < EE; e++) {
            g_offsets[e] = off; g_cursor[e] = off; off += g_counts[e];
        }
    }
    __syncthreads();

    int p0 = atomicAdd(&g_cursor[i0], 1);
    g_list[p0] = t * 2 + 0; g_pos[t * 2 + 0] = p0;
    int p1 = atomicAdd(&g_cursor[i1], 1);
    g_list[p1] = t * 2 + 1; g_pos[t * 2 + 1] = p1;
    __syncthreads();

    if (t == 0) {
        int n = 0;
        for (int e = 0; e < EE; e++) {
            int c = g_counts[e], o = g_offsets[e];
            for (int s = 0; s < c; s += TM) {
                g_tile_e[n]    = e;
                g_tile_row[n]  = o + s;
                g_tile_rows[n] = min(TM, c - s);
                n++;
            }
        }
        g_ntiles = n;
    }
}

// ---------------- gate-up grouped GEMM + silu_and_mul ----------------------
// grid: (MAX_TILES, II/TN). Each block computes the gate tile at column n0 and
// the matching up tile at column II+n0, fuses silu(gate)*up, writes g_act.
__global__ __launch_bounds__(256, 4)
void gateup_kernel(const float* __restrict__ hs, const float* __restrict__ W13)
{
    int bx = blockIdx.x;
    if (bx >= g_ntiles) return;
    int e    = g_tile_e[bx];
    int row0 = g_tile_row[bx];
    int rows = g_tile_rows[bx];
    int n0   = blockIdx.y * TN;

    __shared__ float As[TKB * AS_LD];
    __shared__ float Bg[TKB * TN];
    __shared__ float Bu[TKB * TN];
    __shared__ int   toks[TM];

    int tid = threadIdx.x;
    int ty = tid >> 4, tx = tid & 15;

    if (tid < TM) toks[tid] = (tid < rows) ? (g_list[row0 + tid] >> 1) : -1;
    __syncthreads();

    const float* wg = W13 + (size_t)e * HH * (2 * II);

    float accg[4][4] = {};
    float accu[4][4] = {};

    for (int kk = 0; kk < HH; kk += TKB) {
        // A tile: 64 rows x 32 k (gathered), stored k-major
#pragma unroll
        for (int j = 0; j < 2; j++) {
            int idx = tid + j * 256;       // 512 float4 total
            int m  = idx >> 3;
            int c4 = idx & 7;
            int tok = toks[m];
            float4 v = make_float4(0.f, 0.f, 0.f, 0.f);
            if (tok >= 0)
                v = *(const float4*)(hs + (size_t)tok * HH + kk + c4 * 4);
            As[(c4 * 4 + 0) * AS_LD + m] = v.x;
            As[(c4 * 4 + 1) * AS_LD + m] = v.y;
            As[(c4 * 4 + 2) * AS_LD + m] = v.z;
            As[(c4 * 4 + 3) * AS_LD + m] = v.w;
        }
        // B tiles: gate half at n0, up half at II+n0
#pragma unroll
        for (int j = 0; j < 2; j++) {
            int idx = tid + j * 256;       // 512 float4 total
            int k  = idx >> 4;
            int c4 = idx & 15;
            const float* rowp = wg + (size_t)(kk + k) * (2 * II);
            float4 vg = *(const float4*)(rowp + n0 + c4 * 4);
            float4 vu = *(const float4*)(rowp + II + n0 + c4 * 4);
            *(float4*)&Bg[k * TN + c4 * 4] = vg;
            *(float4*)&Bu[k * TN + c4 * 4] = vu;
        }
        __syncthreads();

#pragma unroll 8
        for (int k = 0; k < TKB; k++) {
            float4 av  = *(const float4*)&As[k * AS_LD + ty * 4];
            float4 bgv = *(const float4*)&Bg[k * TN + tx * 4];
            float4 buv = *(const float4*)&Bu[k * TN + tx * 4];
            float a[4] = {av.x, av.y, av.z, av.w};
            float bg[4] = {bgv.x, bgv.y, bgv.z, bgv.w};
            float bu[4] = {buv.x, buv.y, buv.z, buv.w};
#pragma unroll
            for (int i = 0; i < 4; i++)
#pragma unroll
                for (int jj = 0; jj < 4; jj++) {
                    accg[i][jj] = fmaf(a[i], bg[jj], accg[i][jj]);
                    accu[i][jj] = fmaf(a[i], bu[jj], accu[i][jj]);
                }
        }
        __syncthreads();
    }

    // epilogue: silu(gate) * up -> g_act at sorted position
#pragma unroll
    for (int i = 0; i < 4; i++) {
        int m = ty * 4 + i;
        if (m < rows) {
            int p = row0 + m;
            float4 o;
            float g0 = accg[i][0], g1 = accg[i][1], g2 = accg[i][2], g3 = accg[i][3];
            o.x = (g0 / (1.0f + expf(-g0))) * accu[i][0];
            o.y = (g1 / (1.0f + expf(-g1))) * accu[i][1];
            o.z = (g2 / (1.0f + expf(-g2))) * accu[i][2];
            o.w = (g3 / (1.0f + expf(-g3))) * accu[i][3];
            *(float4*)&g_act[(size_t)p * II + n0 + tx * 4] = o;
        }
    }
}

// ---------------- down grouped GEMM (A contiguous), pre-weighted -----------
__global__ __launch_bounds__(256, 4)
void down_kernel(const float* __restrict__ W2)
{
    int bx = blockIdx.x;
    if (bx >= g_ntiles) return;
    int e    = g_tile_e[bx];
    int row0 = g_tile_row[bx];
    int rows = g_tile_rows[bx];
    int n0   = blockIdx.y * TN;

    __shared__ float As[TKB * AS_LD];
    __shared__ float Bs[TKB * TN];

    int tid = threadIdx.x;
    int ty = tid >> 4, tx = tid & 15;

    const float* w2 = W2 + (size_t)e * II * HH;

    float acc[4][4] = {};

    for (int kk = 0; kk < II; kk += TKB) {
#pragma unroll
        for (int j = 0; j < 2; j++) {
            int idx = tid + j * 256;
            int m  = idx >> 3;
            int c4 = idx & 7;
            float4 v = make_float4(0.f, 0.f, 0.f, 0.f);
            if (m < rows)
                v = *(const float4*)&g_act[(size_t)(row0 + m) * II + kk + c4 * 4];
            As[(c4 * 4 + 0) * AS_LD + m] = v.x;
            As[(c4 * 4 + 1) * AS_LD + m] = v.y;
            As[(c4 * 4 + 2) * AS_LD + m] = v.z;
            As[(c4 * 4 + 3) * AS_LD + m] = v.w;
        }
#pragma unroll
        for (int j = 0; j < 2; j++) {
            int idx = tid + j * 256;
            int k  = idx >> 4;
            int c4 = idx & 15;
            float4 v = *(const float4*)(w2 + (size_t)(kk + k) * HH + n0 + c4 * 4);
            *(float4*)&Bs[k * TN + c4 * 4] = v;
        }
        __syncthreads();

#pragma unroll 8
        for (int k = 0; k < TKB; k++) {
            float4 av = *(const float4*)&As[k * AS_LD + ty * 4];
            float4 bv = *(const float4*)&Bs[k * TN + tx * 4];
            float a[4] = {av.x, av.y, av.z, av.w};
            float b[4] = {bv.x, bv.y, bv.z, bv.w};
#pragma unroll
            for (int i = 0; i < 4; i++)
#pragma unroll
                for (int jj = 0; jj < 4; jj++)
                    acc[i][jj] = fmaf(a[i], b[jj], acc[i][jj]);
        }
        __syncthreads();
    }

#pragma unroll
    for (int i = 0; i < 4; i++) {
        int m = ty * 4 + i;
        if (m < rows) {
            int p = row0 + m;
            float w = g_w[g_list[p]];
            float4 o;
            o.x = w * acc[i][0];
            o.y = w * acc[i][1];
            o.z = w * acc[i][2];
            o.w = w * acc[i][3];
            *(float4*)&g_down[(size_t)p * HH + n0 + tx * 4] = o;
        }
    }
}

// ---------------- combine: out[t] = down[pos(t,0)] + down[pos(t,1)] --------
__global__ void combine_kernel(float* __restrict__ out)
{
    int idx = blockIdx.x * blockDim.x + threadIdx.x;  // T*H/4 float4 elems
    int t = idx / (HH / 4);
    int c = idx % (HH / 4);
    int p0 = g_pos[t * 2 + 0];
    int p1 = g_pos[t * 2 + 1];
    float4 a = *(const float4*)&g_down[(size_t)p0 * HH + c * 4];
    float4 b = *(const float4*)&g_down[(size_t)p1 * HH + c * 4];
    float4 o;
    o.x = a.x + b.x; o.y = a.y + b.y; o.z = a.z + b.z; o.w = a.w + b.w;
    *(float4*)(out + (size_t)t * HH + c * 4) = o;
}

// ---------------- launch ----------------------------------------------------
extern "C" void kernel_launch(void* const* d_in, const int* in_sizes, int n_in,
                              void* d_out, int out_size)
{
    const float* hs     = (const float*)d_in[0];  // [T, H]
    const float* logits = (const float*)d_in[1];  // [T, E]
    const float* W13    = (const float*)d_in[2];  // [E, H, 2I]
    const float* W2     = (const float*)d_in[3];  // [E, I, H]
    float* out = (float*)d_out;                   // [T, H]

    route_kernel<<<1, TT>>>(logits);
    gateup_kernel<<<dim3(MAX_TILES, II / TN), 256>>>(hs, W13);
    down_kernel<<<dim3(MAX_TILES, HH / TN), 256>>>(W2);
    combine_kernel<<<(TT * HH / 4) / 256, 256>>>(out);
}